// round 15
// baseline (speedup 1.0000x reference)
#include <cuda_runtime.h>

#define FULLMASK 0xffffffffu
typedef unsigned long long u64;

constexpr int NPB  = 4;           // nodes (=warps) per block
constexpr int MAXN = 50001;

__device__ int   g_starts[MAXN];
__device__ float g_a1[(MAXN - 1) * 8];

// ---------- packed f32x2 helpers ----------
__device__ __forceinline__ u64 pack2(float lo, float hi) {
    u64 r; asm("mov.b64 %0,{%1,%2};" : "=l"(r) : "f"(lo), "f"(hi)); return r;
}
__device__ __forceinline__ u64 splat2(float v) {
    u64 r; asm("mov.b64 %0,{%1,%1};" : "=l"(r) : "f"(v)); return r;
}
__device__ __forceinline__ void unpack2(u64 v, float& lo, float& hi) {
    asm("mov.b64 {%0,%1},%2;" : "=f"(lo), "=f"(hi) : "l"(v));
}
__device__ __forceinline__ u64 fma2(u64 a, u64 b, u64 c) {
    u64 d; asm("fma.rn.f32x2 %0,%1,%2,%3;" : "=l"(d) : "l"(a), "l"(b), "l"(c)); return d;
}
__device__ __forceinline__ float elu1(float x) {
    return x > 0.0f ? x : (__expf(x) - 1.0f);
}

// 32-lane reduce of 8 partials; lane ends with head lane>>2
__device__ __forceinline__ float reduce8_32(const float p[8], int lane) {
    bool b4 = (lane & 16) != 0;
    float q[4];
#pragma unroll
    for (int j = 0; j < 4; ++j) {
        float send = b4 ? p[j] : p[j + 4];
        float recv = __shfl_xor_sync(FULLMASK, send, 16);
        q[j] = (b4 ? p[j + 4] : p[j]) + recv;
    }
    bool b3 = (lane & 8) != 0;
    float r[2];
#pragma unroll
    for (int j = 0; j < 2; ++j) {
        float send = b3 ? q[j] : q[j + 2];
        float recv = __shfl_xor_sync(FULLMASK, send, 8);
        r[j] = (b3 ? q[j + 2] : q[j]) + recv;
    }
    bool b2 = (lane & 4) != 0;
    float send = b2 ? r[0] : r[1];
    float recv = __shfl_xor_sync(FULLMASK, send, 4);
    float s = (b2 ? r[1] : r[0]) + recv;
    s += __shfl_xor_sync(FULLMASK, s, 2);
    s += __shfl_xor_sync(FULLMASK, s, 1);
    return s;
}

// ---------- prep: CSR row starts (edge-parallel) + a1 (warp-per-node) ----------
__global__ __launch_bounds__(256, 8)
void prep_kernel(const int* __restrict__ seg,
                 const float* __restrict__ features,
                 const float* __restrict__ attn1,
                 int N, int E) {
    const int gtid = blockIdx.x * blockDim.x + threadIdx.x;

    if (gtid < E) {
        int s = seg[gtid];
        int p = (gtid == 0) ? -1 : seg[gtid - 1];
        for (int n = p + 1; n <= s; ++n) g_starts[n] = gtid;
        if (gtid == E - 1)
            for (int n = s + 1; n <= N; ++n) g_starts[n] = E;
    }

    const int lane = threadIdx.x & 31;
    const int n = gtid >> 5;
    if (n < N) {
        float2 f = *(const float2*)(features + (size_t)n * 64 + 2 * lane);
        float p1[8];
#pragma unroll
        for (int h = 0; h < 8; ++h) {
            float2 a = *(const float2*)(attn1 + h * 64 + 2 * lane);
            p1[h] = f.x * a.x + f.y * a.y;
        }
        float v = reduce8_32(p1, lane);
        if ((lane & 3) == 0) g_a1[n * 8 + (lane >> 2)] = v;
    }
}

// ---------- main kernel: warp per node, warp-local 16-edge sweeps ----------
__global__ __launch_bounds__(128, 7)
void gat_main_kernel(const float* __restrict__ emb,
                     const float* __restrict__ attn2,
                     float*       __restrict__ out,
                     int N, int E)
{
    __shared__ float4 s_stage[NPB][16][16];   // [warp][edge][chunk], chunk idx swizzled (16KB)
    __shared__ float  s_w[NPB][16][8];        // per-warp weight mailbox (2KB)
    __shared__ float4 s_a2[8][16];            // attn2 [head][16B-chunk] (2KB)

    const int tid  = threadIdx.x;
    const int lane = tid & 31;
    const int wid  = tid >> 5;

    // attn2 -> smem (128 float4s, one per thread)
    {
        const float4* a2f4 = (const float4*)attn2;
        s_a2[tid >> 4][tid & 15] = a2f4[tid];
    }
    __syncthreads();                          // only block barrier in the kernel

    const int n = blockIdx.x * NPB + wid;
    if (n >= N) return;

    const int s0 = g_starts[n];
    const int e0 = g_starts[n + 1];

    const int el  = lane & 15;                // this lane's edge slot within a sweep
    const int hh  = lane >> 4;                // head half (0: heads 0-3, 1: heads 4-7)
    const int lhi = lane >> 4;                // stage: edge parity
    const int lc  = lane & 15;                // stage: chunk index

    // a1 loop-invariant: all edges of this warp belong to node n
    const float4 a1v = *(const float4*)(g_a1 + n * 8 + hh * 4);

    const float4* __restrict__ ef4 = (const float4*)emb;
    const u64 Z = 0ull;

    u64 accx[4], accy[4];                     // head-pair packed accumulators
#pragma unroll
    for (int hp = 0; hp < 4; ++hp) { accx[hp] = Z; accy[hp] = Z; }
    float dn4[4] = {0.0f, 0.0f, 0.0f, 0.0f};  // per-lane denom partials (heads 4hh+k)

    for (int eb = s0; eb < e0; eb += 16) {
        // ---- stage 16 edges x 256B (coalesced LDG.128, swizzled STS.128) ----
        if (eb + 16 <= E) {
            // fast path: affine, immediate-offset loads (no per-load min/IMAD)
            const float4* gp = ef4 + (size_t)eb * 16 + lhi * 16 + lc;
#pragma unroll
            for (int it = 0; it < 8; ++it)
                s_stage[wid][2 * it + lhi][lc ^ (2 * it + lhi)] = gp[it * 32];
        } else {
            // slow path (last node only): clamp to E-1; garbage slots masked later
#pragma unroll
            for (int it = 0; it < 8; ++it) {
                int e = 2 * it + lhi;
                int ge = min(eb + e, E - 1);
                s_stage[wid][e][lc ^ e] = ef4[(size_t)ge * 16 + lc];
            }
        }
        __syncwarp();

        // ---- dot: lane = (edge el, heads [4hh,4hh+4)), all 64 dims from smem ----
        u64 d[4] = {Z, Z, Z, Z};
#pragma unroll
        for (int c = 0; c < 16; ++c) {
            float4 ev = s_stage[wid][el][c ^ el];
            u64 ep0 = pack2(ev.x, ev.y), ep1 = pack2(ev.z, ev.w);
#pragma unroll
            for (int k = 0; k < 4; ++k) {
                float4 av = s_a2[hh * 4 + k][c];
                d[k] = fma2(ep0, pack2(av.x, av.y), d[k]);
                d[k] = fma2(ep1, pack2(av.z, av.w), d[k]);
            }
        }

        // ---- epilogue: leaky + exp, mailbox store, lane-local denom ----
        const bool valid = (eb + el) < e0;
        float wv[4];
#pragma unroll
        for (int k = 0; k < 4; ++k) {
            float lo, hi; unpack2(d[k], lo, hi);
            float sc = ((const float*)&a1v)[k] + (lo + hi);
            sc = fmaxf(sc, 0.2f * sc);        // leaky relu
            // no-max softmax: scores bounded, exp cannot overflow fp32
            wv[k] = valid ? __expf(sc) : 0.0f;
            dn4[k] += wv[k];
        }
        *(float4*)&s_w[wid][el][hh * 4] = make_float4(wv[0], wv[1], wv[2], wv[3]);
        __syncwarp();

        // ---- agg: emb pairs straight from the stage (LDS.64, conflict-free) ----
        const int m = min(16, e0 - eb);       // warp-uniform
#pragma unroll 2
        for (int e = 0; e < m; ++e) {
            const float4* wrow = (const float4*)s_w[wid][e];
            float4 wa = wrow[0];              // heads 0-3 (broadcast LDS.128)
            float4 wb = wrow[1];              // heads 4-7
            const char* cp = (const char*)&s_stage[wid][e][(lane >> 1) ^ e];
            u64 c2 = *(const u64*)(cp + (lane & 1) * 8);   // {emb[2l], emb[2l+1]}
            float clo, chi; unpack2(c2, clo, chi);
            u64 w01 = pack2(wa.x, wa.y), w23 = pack2(wa.z, wa.w);
            u64 w45 = pack2(wb.x, wb.y), w67 = pack2(wb.z, wb.w);
            u64 cx = splat2(clo), cy = splat2(chi);
            accx[0] = fma2(w01, cx, accx[0]);  accy[0] = fma2(w01, cy, accy[0]);
            accx[1] = fma2(w23, cx, accx[1]);  accy[1] = fma2(w23, cy, accy[1]);
            accx[2] = fma2(w45, cx, accx[2]);  accy[2] = fma2(w45, cy, accy[2]);
            accx[3] = fma2(w67, cx, accx[3]);  accy[3] = fma2(w67, cy, accy[3]);
        }
        __syncwarp();                         // stage/w reused next sweep
    }

    // ---- denominator: xor-tree over the 16 el-lanes of each head half ----
#pragma unroll
    for (int dstep = 1; dstep < 16; dstep <<= 1) {
#pragma unroll
        for (int k = 0; k < 4; ++k)
            dn4[k] += __shfl_xor_sync(FULLMASK, dn4[k], dstep);
    }
    // publish head-half denoms so every lane can read all 8
    if (el == 0)
        *(float4*)&s_w[wid][0][hh * 4] = make_float4(dn4[0], dn4[1], dn4[2], dn4[3]);
    __syncwarp();
    float4 dhA = *(const float4*)&s_w[wid][0][0];   // heads 0-3
    float4 dhB = *(const float4*)&s_w[wid][0][4];   // heads 4-7
    float dall[8] = {dhA.x, dhA.y, dhA.z, dhA.w, dhB.x, dhB.y, dhB.z, dhB.w};

    // ---- finalize: normalize, ELU, store (lane owns dims {2l, 2l+1}) ----
    float* op = out + (size_t)n * 512 + 2 * lane;
#pragma unroll
    for (int hp = 0; hp < 4; ++hp) {
        float dA_ = dall[2 * hp], dB_ = dall[2 * hp + 1];
        float iA = dA_ > 0.0f ? __frcp_rn(dA_) : 1.0f;
        float iB = dB_ > 0.0f ? __frcp_rn(dB_) : 1.0f;
        float xA, xB, yA, yB;
        unpack2(accx[hp], xA, xB);
        unpack2(accy[hp], yA, yB);
        *(float2*)(op + (2 * hp)     * 64) = make_float2(elu1(xA * iA), elu1(yA * iA));
        *(float2*)(op + (2 * hp + 1) * 64) = make_float2(elu1(xB * iB), elu1(yB * iB));
    }
}

extern "C" void kernel_launch(void* const* d_in, const int* in_sizes, int n_in,
                              void* d_out, int out_size) {
    const float* features = (const float*)d_in[0];
    const float* emb      = (const float*)d_in[1];
    const float* attn1    = (const float*)d_in[2];
    const float* attn2    = (const float*)d_in[3];
    const int*   seg      = (const int*)d_in[4];
    float* out = (float*)d_out;

    int N = in_sizes[0] / 64;    // 50000
    int E = in_sizes[4];         // 1250000

    int prepThreads = (N * 32 > E) ? N * 32 : E;
    prep_kernel<<<(prepThreads + 255) / 256, 256>>>(seg, features, attn1, N, E);

    int blocks = (N + NPB - 1) / NPB;
    gat_main_kernel<<<blocks, NPB * 32>>>(emb, attn2, out, N, E);
}

// round 16
// speedup vs baseline: 1.1422x; 1.1422x over previous
#include <cuda_runtime.h>

#define FULLMASK 0xffffffffu
typedef unsigned long long u64;

constexpr int NPB  = 4;           // nodes (=warps) per block
constexpr int MAXN = 50001;

__device__ int   g_starts[MAXN];
__device__ float g_a1[(MAXN - 1) * 8];

// ---------- packed f32x2 helpers ----------
__device__ __forceinline__ u64 pack2(float lo, float hi) {
    u64 r; asm("mov.b64 %0,{%1,%2};" : "=l"(r) : "f"(lo), "f"(hi)); return r;
}
__device__ __forceinline__ u64 splat2(float v) {
    u64 r; asm("mov.b64 %0,{%1,%1};" : "=l"(r) : "f"(v)); return r;
}
__device__ __forceinline__ void unpack2(u64 v, float& lo, float& hi) {
    asm("mov.b64 {%0,%1},%2;" : "=f"(lo), "=f"(hi) : "l"(v));
}
__device__ __forceinline__ u64 fma2(u64 a, u64 b, u64 c) {
    u64 d; asm("fma.rn.f32x2 %0,%1,%2,%3;" : "=l"(d) : "l"(a), "l"(b), "l"(c)); return d;
}
__device__ __forceinline__ float elu1(float x) {
    return x > 0.0f ? x : (__expf(x) - 1.0f);
}
__device__ __forceinline__ unsigned s2u(const void* p) {
    return (unsigned)__cvta_generic_to_shared(p);
}

// 32-lane reduce of 8 partials; lane ends with head lane>>2
__device__ __forceinline__ float reduce8_32(const float p[8], int lane) {
    bool b4 = (lane & 16) != 0;
    float q[4];
#pragma unroll
    for (int j = 0; j < 4; ++j) {
        float send = b4 ? p[j] : p[j + 4];
        float recv = __shfl_xor_sync(FULLMASK, send, 16);
        q[j] = (b4 ? p[j + 4] : p[j]) + recv;
    }
    bool b3 = (lane & 8) != 0;
    float r[2];
#pragma unroll
    for (int j = 0; j < 2; ++j) {
        float send = b3 ? q[j] : q[j + 2];
        float recv = __shfl_xor_sync(FULLMASK, send, 8);
        r[j] = (b3 ? q[j + 2] : q[j]) + recv;
    }
    bool b2 = (lane & 4) != 0;
    float send = b2 ? r[0] : r[1];
    float recv = __shfl_xor_sync(FULLMASK, send, 4);
    float s = (b2 ? r[1] : r[0]) + recv;
    s += __shfl_xor_sync(FULLMASK, s, 2);
    s += __shfl_xor_sync(FULLMASK, s, 1);
    return s;
}

// ---------- prep: CSR row starts (edge-parallel) + a1 (warp-per-node) ----------
__global__ __launch_bounds__(256, 8)
void prep_kernel(const int* __restrict__ seg,
                 const float* __restrict__ features,
                 const float* __restrict__ attn1,
                 int N, int E) {
    const int gtid = blockIdx.x * blockDim.x + threadIdx.x;

    if (gtid < E) {
        int s = seg[gtid];
        int p = (gtid == 0) ? -1 : seg[gtid - 1];
        for (int n = p + 1; n <= s; ++n) g_starts[n] = gtid;
        if (gtid == E - 1)
            for (int n = s + 1; n <= N; ++n) g_starts[n] = E;
    }

    const int lane = threadIdx.x & 31;
    const int n = gtid >> 5;
    if (n < N) {
        float2 f = *(const float2*)(features + (size_t)n * 64 + 2 * lane);
        float p1[8];
#pragma unroll
        for (int h = 0; h < 8; ++h) {
            float2 a = *(const float2*)(attn1 + h * 64 + 2 * lane);
            p1[h] = f.x * a.x + f.y * a.y;
        }
        float v = reduce8_32(p1, lane);
        if ((lane & 3) == 0) g_a1[n * 8 + (lane >> 2)] = v;
    }
}

// issue one 16-edge stage into buf via cp.async (per-warp), then commit
__device__ __forceinline__ void stage_sweep(float4 (*stg)[16], const float4* __restrict__ ef4,
                                            int eb, int E, int lhi, int lc) {
    if (eb + 16 <= E) {
        // fast path: affine immediate-offset sources
        const float4* gp = ef4 + (size_t)eb * 16 + lhi * 16 + lc;
#pragma unroll
        for (int it = 0; it < 8; ++it) {
            unsigned dst = s2u(&stg[2 * it + lhi][lc ^ (2 * it + lhi)]);
            asm volatile("cp.async.cg.shared.global [%0], [%1], 16;"
                         :: "r"(dst), "l"(gp + it * 32));
        }
    } else {
        // tail path: clamp to E-1; garbage slots masked by `valid` later
#pragma unroll
        for (int it = 0; it < 8; ++it) {
            int e = 2 * it + lhi;
            int ge = min(eb + e, E - 1);
            unsigned dst = s2u(&stg[e][lc ^ e]);
            asm volatile("cp.async.cg.shared.global [%0], [%1], 16;"
                         :: "r"(dst), "l"(ef4 + (size_t)ge * 16 + lc));
        }
    }
    asm volatile("cp.async.commit_group;" ::: "memory");
}

// ---------- main kernel: warp per node, cp.async double-buffered 16-edge sweeps ----------
__global__ __launch_bounds__(128, 6)
void gat_main_kernel(const float* __restrict__ emb,
                     const float* __restrict__ attn2,
                     float*       __restrict__ out,
                     int N, int E)
{
    __shared__ float4 s_stage[NPB][2][16][16]; // [warp][buf][edge][chunk], swizzled (32KB)
    __shared__ float  s_w[NPB][16][8];         // per-warp weight mailbox (2KB)
    __shared__ float4 s_a2[8][16];             // attn2 [head][16B-chunk] (2KB)

    const int tid  = threadIdx.x;
    const int lane = tid & 31;
    const int wid  = tid >> 5;

    // attn2 -> smem (128 float4s, one per thread)
    {
        const float4* a2f4 = (const float4*)attn2;
        s_a2[tid >> 4][tid & 15] = a2f4[tid];
    }
    __syncthreads();                           // only block barrier in the kernel

    const int n = blockIdx.x * NPB + wid;
    if (n >= N) return;

    const int s0 = g_starts[n];
    const int e0 = g_starts[n + 1];

    const int el  = lane & 15;                 // this lane's edge slot within a sweep
    const int hh  = lane >> 4;                 // head half (0: heads 0-3, 1: heads 4-7)
    const int lhi = lane >> 4;                 // stage: edge parity
    const int lc  = lane & 15;                 // stage: chunk index

    // a1 loop-invariant: all edges of this warp belong to node n
    const float4 a1v = *(const float4*)(g_a1 + n * 8 + hh * 4);

    const float4* __restrict__ ef4 = (const float4*)emb;
    const u64 Z = 0ull;

    u64 accx[4], accy[4];                      // head-pair packed accumulators
#pragma unroll
    for (int hp = 0; hp < 4; ++hp) { accx[hp] = Z; accy[hp] = Z; }
    float dn4[4] = {0.0f, 0.0f, 0.0f, 0.0f};   // per-lane denom partials

    const int nSw = (e0 - s0 + 15) >> 4;
    if (nSw > 0) stage_sweep(s_stage[wid][0], ef4, s0, E, lhi, lc);

    for (int t = 0; t < nSw; ++t) {
        const int eb  = s0 + t * 16;
        const int buf = t & 1;

        if (t + 1 < nSw) {
            stage_sweep(s_stage[wid][buf ^ 1], ef4, eb + 16, E, lhi, lc);  // prefetch
            asm volatile("cp.async.wait_group 1;" ::: "memory");           // wait current only
        } else {
            asm volatile("cp.async.wait_group 0;" ::: "memory");
        }
        __syncwarp();                          // all lanes' staged data visible

        // ---- dot: lane = (edge el, heads [4hh,4hh+4)), all 64 dims from smem ----
        u64 d[4] = {Z, Z, Z, Z};
#pragma unroll
        for (int c = 0; c < 16; ++c) {
            float4 ev = s_stage[wid][buf][el][c ^ el];
            u64 ep0 = pack2(ev.x, ev.y), ep1 = pack2(ev.z, ev.w);
#pragma unroll
            for (int k = 0; k < 4; ++k) {
                float4 av = s_a2[hh * 4 + k][c];
                d[k] = fma2(ep0, pack2(av.x, av.y), d[k]);
                d[k] = fma2(ep1, pack2(av.z, av.w), d[k]);
            }
        }

        // ---- epilogue: leaky + exp, mailbox store, lane-local denom ----
        const bool valid = (eb + el) < e0;
        float wv[4];
#pragma unroll
        for (int k = 0; k < 4; ++k) {
            float lo, hi; unpack2(d[k], lo, hi);
            float sc = ((const float*)&a1v)[k] + (lo + hi);
            sc = fmaxf(sc, 0.2f * sc);         // leaky relu
            // no-max softmax: scores bounded, exp cannot overflow fp32
            wv[k] = valid ? __expf(sc) : 0.0f;
            dn4[k] += wv[k];
        }
        *(float4*)&s_w[wid][el][hh * 4] = make_float4(wv[0], wv[1], wv[2], wv[3]);
        __syncwarp();

        // ---- agg: emb pairs straight from the stage (LDS.64, conflict-free) ----
        const int m = min(16, e0 - eb);        // warp-uniform
#pragma unroll 2
        for (int e = 0; e < m; ++e) {
            const float4* wrow = (const float4*)s_w[wid][e];
            float4 wa = wrow[0];               // heads 0-3 (broadcast LDS.128)
            float4 wb = wrow[1];               // heads 4-7
            const char* cp = (const char*)&s_stage[wid][buf][e][(lane >> 1) ^ e];
            u64 c2 = *(const u64*)(cp + (lane & 1) * 8);   // {emb[2l], emb[2l+1]}
            float clo, chi; unpack2(c2, clo, chi);
            u64 w01 = pack2(wa.x, wa.y), w23 = pack2(wa.z, wa.w);
            u64 w45 = pack2(wb.x, wb.y), w67 = pack2(wb.z, wb.w);
            u64 cx = splat2(clo), cy = splat2(chi);
            accx[0] = fma2(w01, cx, accx[0]);  accy[0] = fma2(w01, cy, accy[0]);
            accx[1] = fma2(w23, cx, accx[1]);  accy[1] = fma2(w23, cy, accy[1]);
            accx[2] = fma2(w45, cx, accx[2]);  accy[2] = fma2(w45, cy, accy[2]);
            accx[3] = fma2(w67, cx, accx[3]);  accy[3] = fma2(w67, cy, accy[3]);
        }
        // no trailing sync needed: next prefetch targets the other buffer, and
        // same-warp MIO order puts these LDS ahead of any later cp.async write
    }

    // ---- denominator: xor-tree over the 16 el-lanes of each head half ----
#pragma unroll
    for (int dstep = 1; dstep < 16; dstep <<= 1) {
#pragma unroll
        for (int k = 0; k < 4; ++k)
            dn4[k] += __shfl_xor_sync(FULLMASK, dn4[k], dstep);
    }
    if (el == 0)
        *(float4*)&s_w[wid][0][hh * 4] = make_float4(dn4[0], dn4[1], dn4[2], dn4[3]);
    __syncwarp();
    float4 dhA = *(const float4*)&s_w[wid][0][0];   // heads 0-3
    float4 dhB = *(const float4*)&s_w[wid][0][4];   // heads 4-7
    float dall[8] = {dhA.x, dhA.y, dhA.z, dhA.w, dhB.x, dhB.y, dhB.z, dhB.w};

    // ---- finalize: normalize, ELU, store (lane owns dims {2l, 2l+1}) ----
    float* op = out + (size_t)n * 512 + 2 * lane;
#pragma unroll
    for (int hp = 0; hp < 4; ++hp) {
        float dA_ = dall[2 * hp], dB_ = dall[2 * hp + 1];
        float iA = dA_ > 0.0f ? __frcp_rn(dA_) : 1.0f;
        float iB = dB_ > 0.0f ? __frcp_rn(dB_) : 1.0f;
        float xA, xB, yA, yB;
        unpack2(accx[hp], xA, xB);
        unpack2(accy[hp], yA, yB);
        *(float2*)(op + (2 * hp)     * 64) = make_float2(elu1(xA * iA), elu1(yA * iA));
        *(float2*)(op + (2 * hp + 1) * 64) = make_float2(elu1(xB * iB), elu1(yB * iB));
    }
}

extern "C" void kernel_launch(void* const* d_in, const int* in_sizes, int n_in,
                              void* d_out, int out_size) {
    const float* features = (const float*)d_in[0];
    const float* emb      = (const float*)d_in[1];
    const float* attn1    = (const float*)d_in[2];
    const float* attn2    = (const float*)d_in[3];
    const int*   seg      = (const int*)d_in[4];
    float* out = (float*)d_out;

    int N = in_sizes[0] / 64;    // 50000
    int E = in_sizes[4];         // 1250000

    int prepThreads = (N * 32 > E) ? N * 32 : E;
    prep_kernel<<<(prepThreads + 255) / 256, 256>>>(seg, features, attn1, N, E);

    int blocks = (N + NPB - 1) / NPB;
    gat_main_kernel<<<blocks, NPB * 32>>>(emb, attn2, out, N, E);
}

// round 17
// speedup vs baseline: 1.2479x; 1.0925x over previous
#include <cuda_runtime.h>

#define FULLMASK 0xffffffffu
typedef unsigned long long u64;

constexpr int NPB  = 4;           // nodes (=warps) per block
constexpr int MAXN = 50001;

__device__ int   g_starts[MAXN];
__device__ float g_a1[(MAXN - 1) * 8];

// ---------- packed f32x2 helpers ----------
__device__ __forceinline__ u64 pack2(float lo, float hi) {
    u64 r; asm("mov.b64 %0,{%1,%2};" : "=l"(r) : "f"(lo), "f"(hi)); return r;
}
__device__ __forceinline__ u64 splat2(float v) {
    u64 r; asm("mov.b64 %0,{%1,%1};" : "=l"(r) : "f"(v)); return r;
}
__device__ __forceinline__ void unpack2(u64 v, float& lo, float& hi) {
    asm("mov.b64 {%0,%1},%2;" : "=f"(lo), "=f"(hi) : "l"(v));
}
__device__ __forceinline__ u64 fma2(u64 a, u64 b, u64 c) {
    u64 d; asm("fma.rn.f32x2 %0,%1,%2,%3;" : "=l"(d) : "l"(a), "l"(b), "l"(c)); return d;
}
__device__ __forceinline__ u64 add2(u64 a, u64 b) {
    u64 d; asm("add.rn.f32x2 %0,%1,%2;" : "=l"(d) : "l"(a), "l"(b)); return d;
}
__device__ __forceinline__ float elu1(float x) {
    return x > 0.0f ? x : (__expf(x) - 1.0f);
}
__device__ __forceinline__ unsigned s2u(const void* p) {
    return (unsigned)__cvta_generic_to_shared(p);
}

// 32-lane reduce of 8 partials; lane ends with head lane>>2
__device__ __forceinline__ float reduce8_32(const float p[8], int lane) {
    bool b4 = (lane & 16) != 0;
    float q[4];
#pragma unroll
    for (int j = 0; j < 4; ++j) {
        float send = b4 ? p[j] : p[j + 4];
        float recv = __shfl_xor_sync(FULLMASK, send, 16);
        q[j] = (b4 ? p[j + 4] : p[j]) + recv;
    }
    bool b3 = (lane & 8) != 0;
    float r[2];
#pragma unroll
    for (int j = 0; j < 2; ++j) {
        float send = b3 ? q[j] : q[j + 2];
        float recv = __shfl_xor_sync(FULLMASK, send, 8);
        r[j] = (b3 ? q[j + 2] : q[j]) + recv;
    }
    bool b2 = (lane & 4) != 0;
    float send = b2 ? r[0] : r[1];
    float recv = __shfl_xor_sync(FULLMASK, send, 4);
    float s = (b2 ? r[1] : r[0]) + recv;
    s += __shfl_xor_sync(FULLMASK, s, 2);
    s += __shfl_xor_sync(FULLMASK, s, 1);
    return s;
}

// ---------- prep: CSR row starts (edge-parallel) + a1 (warp-per-node) ----------
__global__ __launch_bounds__(256, 8)
void prep_kernel(const int* __restrict__ seg,
                 const float* __restrict__ features,
                 const float* __restrict__ attn1,
                 int N, int E) {
    const int gtid = blockIdx.x * blockDim.x + threadIdx.x;

    if (gtid < E) {
        int s = seg[gtid];
        int p = (gtid == 0) ? -1 : seg[gtid - 1];
        for (int n = p + 1; n <= s; ++n) g_starts[n] = gtid;
        if (gtid == E - 1)
            for (int n = s + 1; n <= N; ++n) g_starts[n] = E;
    }

    const int lane = threadIdx.x & 31;
    const int n = gtid >> 5;
    if (n < N) {
        float2 f = *(const float2*)(features + (size_t)n * 64 + 2 * lane);
        float p1[8];
#pragma unroll
        for (int h = 0; h < 8; ++h) {
            float2 a = *(const float2*)(attn1 + h * 64 + 2 * lane);
            p1[h] = f.x * a.x + f.y * a.y;
        }
        float v = reduce8_32(p1, lane);
        if ((lane & 3) == 0) g_a1[n * 8 + (lane >> 2)] = v;
    }
}

// issue one 16-edge stage into buf via cp.async (per-warp), then commit
__device__ __forceinline__ void stage_sweep(float4 (*stg)[16], const float4* __restrict__ ef4,
                                            int eb, int E, int lhi, int lc) {
    if (eb + 16 <= E) {
        const float4* gp = ef4 + (size_t)eb * 16 + lhi * 16 + lc;
#pragma unroll
        for (int it = 0; it < 8; ++it) {
            unsigned dst = s2u(&stg[2 * it + lhi][lc ^ (2 * it + lhi)]);
            asm volatile("cp.async.cg.shared.global [%0], [%1], 16;"
                         :: "r"(dst), "l"(gp + it * 32));
        }
    } else {
#pragma unroll
        for (int it = 0; it < 8; ++it) {
            int e = 2 * it + lhi;
            int ge = min(eb + e, E - 1);
            unsigned dst = s2u(&stg[e][lc ^ e]);
            asm volatile("cp.async.cg.shared.global [%0], [%1], 16;"
                         :: "r"(dst), "l"(ef4 + (size_t)ge * 16 + lc));
        }
    }
    asm volatile("cp.async.commit_group;" ::: "memory");
}

// ---------- main kernel: warp per node, cp.async double-buffered 16-edge sweeps ----------
// dot geometry: lane = (el = lane&7 -> edges {el, el+8}; hh = bit3 -> heads [4hh,4hh+4);
//               ch = bit4 -> chunks [8ch, 8ch+8))
__global__ __launch_bounds__(128, 6)
void gat_main_kernel(const float* __restrict__ emb,
                     const float* __restrict__ attn2,
                     float*       __restrict__ out,
                     int N, int E)
{
    __shared__ float4 s_stage[NPB][2][16][16]; // [warp][buf][edge][chunk], swizzled (32KB)
    __shared__ float  s_w[NPB][16][8];         // per-warp weight mailbox (2KB)
    // a2 conflict-free layout: index = ch*73 + head*9 + j  (f4 units)
    // ch-stride 1168B (=16 mod 128), head-stride 144B (4 heads -> 576 = 64 mod 128)
    __shared__ float4 s_a2x[148];              // ~2.4KB

    const int tid  = threadIdx.x;
    const int lane = tid & 31;
    const int wid  = tid >> 5;

    // attn2 -> s_a2x (128 float4s, one per thread)
    {
        const float4* a2f4 = (const float4*)attn2;
        int h = tid >> 4, c = tid & 15;
        s_a2x[(c >> 3) * 73 + h * 9 + (c & 7)] = a2f4[tid];
    }
    __syncthreads();                           // only block barrier in the kernel

    const int n = blockIdx.x * NPB + wid;
    if (n >= N) return;

    const int s0 = g_starts[n];
    const int e0 = g_starts[n + 1];

    const int el  = lane & 7;                  // edge pair {el, el+8}
    const int hh  = (lane >> 3) & 1;           // head half
    const int ch  = lane >> 4;                 // chunk half
    const int lhi = lane >> 4;                 // stage: edge parity
    const int lc  = lane & 15;                 // stage: chunk index

    const float4 a1v = *(const float4*)(g_a1 + n * 8 + hh * 4);
    const float4* __restrict__ a2p = s_a2x + ch * 73 + hh * 36;  // 4 heads x 9 each

    const float4* __restrict__ ef4 = (const float4*)emb;
    const u64 Z = 0ull;

    u64 accx[4], accy[4];                      // head-pair packed accumulators (agg)
#pragma unroll
    for (int hp = 0; hp < 4; ++hp) { accx[hp] = Z; accy[hp] = Z; }
    float dn4[4] = {0.0f, 0.0f, 0.0f, 0.0f};   // per-lane denom partials (heads 4hh+k)

    const int eMineOff = el + 8 * ch;          // this lane's owned edge slot (0..15)
    const bool chB = (ch == 1);

    const int nSw = (e0 - s0 + 15) >> 4;
    if (nSw > 0) stage_sweep(s_stage[wid][0], ef4, s0, E, lhi, lc);

    for (int t = 0; t < nSw; ++t) {
        const int eb  = s0 + t * 16;
        const int buf = t & 1;

        if (t + 1 < nSw) {
            stage_sweep(s_stage[wid][buf ^ 1], ef4, eb + 16, E, lhi, lc);  // prefetch
            asm volatile("cp.async.wait_group 1;" ::: "memory");
        } else {
            asm volatile("cp.async.wait_group 0;" ::: "memory");
        }
        __syncwarp();

        // ---- dot: 2 edges x 4 heads x 8 chunks per lane; a2 amortized x2, 1-wf loads ----
        u64 dA[4] = {Z, Z, Z, Z};
        u64 dB[4] = {Z, Z, Z, Z};
#pragma unroll
        for (int j = 0; j < 8; ++j) {
            const int c = 8 * ch + j;
            float4 evA = s_stage[wid][buf][el][c ^ el];
            float4 evB = s_stage[wid][buf][el + 8][c ^ (el + 8)];
            u64 eA0 = pack2(evA.x, evA.y), eA1 = pack2(evA.z, evA.w);
            u64 eB0 = pack2(evB.x, evB.y), eB1 = pack2(evB.z, evB.w);
#pragma unroll
            for (int k = 0; k < 4; ++k) {
                float4 av = a2p[k * 9 + j];
                u64 a0 = pack2(av.x, av.y), a1p_ = pack2(av.z, av.w);
                dA[k] = fma2(eA0, a0, dA[k]);
                dB[k] = fma2(eB0, a0, dB[k]);
                dA[k] = fma2(eA1, a1p_, dA[k]);
                dB[k] = fma2(eB1, a1p_, dB[k]);
            }
        }

        // ---- combine chunk halves: lane keeps edge el+8*ch ----
        u64 dm[4];
#pragma unroll
        for (int k = 0; k < 4; ++k) {
            u64 send = chB ? dA[k] : dB[k];
            u64 recv = __shfl_xor_sync(FULLMASK, send, 16);
            dm[k] = add2(chB ? dB[k] : dA[k], recv);
        }

        // ---- epilogue: leaky + exp, mailbox store, lane-local denom ----
        const bool valid = (eb + eMineOff) < e0;
        float wv[4];
#pragma unroll
        for (int k = 0; k < 4; ++k) {
            float lo, hi; unpack2(dm[k], lo, hi);
            float sc = ((const float*)&a1v)[k] + (lo + hi);
            sc = fmaxf(sc, 0.2f * sc);         // leaky relu
            // no-max softmax: scores bounded, exp cannot overflow fp32
            wv[k] = valid ? __expf(sc) : 0.0f;
            dn4[k] += wv[k];
        }
        *(float4*)&s_w[wid][eMineOff][hh * 4] = make_float4(wv[0], wv[1], wv[2], wv[3]);
        __syncwarp();

        // ---- agg: emb pairs straight from the stage (LDS.64, conflict-free) ----
        const int m = min(16, e0 - eb);        // warp-uniform
#pragma unroll 2
        for (int e = 0; e < m; ++e) {
            const float4* wrow = (const float4*)s_w[wid][e];
            float4 wa = wrow[0];               // heads 0-3 (broadcast LDS.128)
            float4 wb = wrow[1];               // heads 4-7
            const char* cp = (const char*)&s_stage[wid][buf][e][(lane >> 1) ^ e];
            u64 c2 = *(const u64*)(cp + (lane & 1) * 8);   // {emb[2l], emb[2l+1]}
            float clo, chi; unpack2(c2, clo, chi);
            u64 w01 = pack2(wa.x, wa.y), w23 = pack2(wa.z, wa.w);
            u64 w45 = pack2(wb.x, wb.y), w67 = pack2(wb.z, wb.w);
            u64 cx = splat2(clo), cy = splat2(chi);
            accx[0] = fma2(w01, cx, accx[0]);  accy[0] = fma2(w01, cy, accy[0]);
            accx[1] = fma2(w23, cx, accx[1]);  accy[1] = fma2(w23, cy, accy[1]);
            accx[2] = fma2(w45, cx, accx[2]);  accy[2] = fma2(w45, cy, accy[2]);
            accx[3] = fma2(w67, cx, accx[3]);  accy[3] = fma2(w67, cy, accy[3]);
        }
        // next prefetch targets the other buffer; same-warp MIO order protects reads
    }

    // ---- denominator: sum over el (bits 0-2) and ch (bit 4); keep hh (bit 3) ----
#pragma unroll
    for (int k = 0; k < 4; ++k) {
        dn4[k] += __shfl_xor_sync(FULLMASK, dn4[k], 1);
        dn4[k] += __shfl_xor_sync(FULLMASK, dn4[k], 2);
        dn4[k] += __shfl_xor_sync(FULLMASK, dn4[k], 4);
        dn4[k] += __shfl_xor_sync(FULLMASK, dn4[k], 16);
    }
    if (el == 0 && ch == 0)                    // lanes 0 (hh=0) and 8 (hh=1)
        *(float4*)&s_w[wid][0][hh * 4] = make_float4(dn4[0], dn4[1], dn4[2], dn4[3]);
    __syncwarp();
    float4 dhA = *(const float4*)&s_w[wid][0][0];   // heads 0-3
    float4 dhB = *(const float4*)&s_w[wid][0][4];   // heads 4-7
    float dall[8] = {dhA.x, dhA.y, dhA.z, dhA.w, dhB.x, dhB.y, dhB.z, dhB.w};

    // ---- finalize: normalize, ELU, store (lane owns dims {2l, 2l+1}) ----
    float* op = out + (size_t)n * 512 + 2 * lane;
#pragma unroll
    for (int hp = 0; hp < 4; ++hp) {
        float dA_ = dall[2 * hp], dB_ = dall[2 * hp + 1];
        float iA = dA_ > 0.0f ? __frcp_rn(dA_) : 1.0f;
        float iB = dB_ > 0.0f ? __frcp_rn(dB_) : 1.0f;
        float xA, xB, yA, yB;
        unpack2(accx[hp], xA, xB);
        unpack2(accy[hp], yA, yB);
        *(float2*)(op + (2 * hp)     * 64) = make_float2(elu1(xA * iA), elu1(yA * iA));
        *(float2*)(op + (2 * hp + 1) * 64) = make_float2(elu1(xB * iB), elu1(yB * iB));
    }
}

extern "C" void kernel_launch(void* const* d_in, const int* in_sizes, int n_in,
                              void* d_out, int out_size) {
    const float* features = (const float*)d_in[0];
    const float* emb      = (const float*)d_in[1];
    const float* attn1    = (const float*)d_in[2];
    const float* attn2    = (const float*)d_in[3];
    const int*   seg      = (const int*)d_in[4];
    float* out = (float*)d_out;

    int N = in_sizes[0] / 64;    // 50000
    int E = in_sizes[4];         // 1250000

    int prepThreads = (N * 32 > E) ? N * 32 : E;
    prep_kernel<<<(prepThreads + 255) / 256, 256>>>(seg, features, attn1, N, E);

    int blocks = (N + NPB - 1) / NPB;
    gat_main_kernel<<<blocks, NPB * 32>>>(emb, attn2, out, N, E);
}